// round 11
// baseline (speedup 1.0000x reference)
#include <cuda_runtime.h>
#include <cuda_bf16.h>
#include <cstdint>

#define T_DIM 8192
#define K_DIM 2048
#define TM1   (T_DIM - 1)                      // 8191 rows in the loss
#define NTOT  ((long long)TM1 * K_DIM)         // 16,775,168 elements
#define GAMMA 0.99f
#define LOGG  (-0.0100503358535014f)           // logf(0.99)

#define SCAN_BLOCKS  256                       // FIRST block IDs -> spread over all SMs
#define QSUM_BLOCKS  888
#define NBLOCKS      (SCAN_BLOCKS + QSUM_BLOCKS)
#define NQV          (2 * QSUM_BLOCKS + SCAN_BLOCKS)   // 2032 virtual qsum slices
#define FULLM        0xFFFFFFFFu

#define RPAD   68                              // rows-per-col stride (64 + 4): conflict-free
#define NRND   128                             // 128 rounds x 64 rows = 8192 >= TM1

// Scratch (device globals are the allowed scratch mechanism).
// Transposed layout [k][t] so warp-over-rows access is coalesced.
__device__ float2       g_dp  [(long long)K_DIM * TM1];  // {decay, td*decay}
__device__ double       g_part[NBLOCKS];
__device__ unsigned int g_done;                          // zero-init; self-resetting

__device__ __forceinline__ float sl1(float pred, float target) {
    float a = fabsf(pred - target);
    float m = fminf(a, 1.0f);
    return m * (a - 0.5f * m);
}
__device__ __forceinline__ float sl1_acc(float acc, float d) {
    float a = fabsf(d);
    float m = fminf(a, 1.0f);
    return fmaf(m, fmaf(-0.5f, m, a), acc);
}

__device__ __forceinline__ unsigned int smem_u32(const void* p) {
    return (unsigned int)__cvta_generic_to_shared(p);
}
__device__ __forceinline__ void cpa4(unsigned int dst, const float* src) {
    asm volatile("cp.async.ca.shared.global [%0], [%1], 4;" :: "r"(dst), "l"(src));
}
#define CPC()  asm volatile("cp.async.commit_group;")
#define CPW(n) asm volatile("cp.async.wait_group %0;" :: "n"(n))

__global__ void __launch_bounds__(256, 8)
retrace_main(const float* __restrict__ q,
             const float* __restrict__ tq,
             const float* __restrict__ tv,
             const float* __restrict__ r,
             const float* __restrict__ olp,
             const float* __restrict__ tlp,
             float* __restrict__ out)
{
    const int tid  = threadIdx.x;
    const int lane = tid & 31;
    const int wrp  = tid >> 5;
    double acc = 0.0;

    // staging tiles: [buf][col*RPAD + row], 64 rows/round, 8 cols.
    __shared__ float s_liw[2][8 * RPAD];    // forward: tlp ; backward: q tile
    __shared__ float s_r  [2][8 * RPAD];    // forward: r   ; backward: dp.x plane
    __shared__ float s_tv [2][8 * RPAD];    // forward: tv  ; backward: dp.y plane
    __shared__ float s_tq [2][8 * RPAD];
    __shared__ int   s_nch[8];

    // -------- qsum slice: virtual id v in [0, NQV); deterministic per block --------
    const float4* q4 = (const float4*)q;
    const long long nvec = NTOT / 4;
    auto qsum_slice = [&](int v) {
        long long idx = (long long)v * 256 + tid;
        const long long stride = (long long)NQV * 256;
        float f0 = 0.0f, f1 = 0.0f, f2 = 0.0f, f3 = 0.0f;
        for (; idx + 3 * stride < nvec; idx += 4 * stride) {
            float4 a = q4[idx];
            float4 b = q4[idx + stride];
            float4 c = q4[idx + 2 * stride];
            float4 d = q4[idx + 3 * stride];
            f0 = sl1_acc(sl1_acc(sl1_acc(sl1_acc(f0, a.x), a.y), a.z), a.w);
            f1 = sl1_acc(sl1_acc(sl1_acc(sl1_acc(f1, b.x), b.y), b.z), b.w);
            f2 = sl1_acc(sl1_acc(sl1_acc(sl1_acc(f2, c.x), c.y), c.z), c.w);
            f3 = sl1_acc(sl1_acc(sl1_acc(sl1_acc(f3, d.x), d.y), d.z), d.w);
        }
        for (; idx < nvec; idx += stride) {
            float4 a = q4[idx];
            f0 = sl1_acc(sl1_acc(sl1_acc(sl1_acc(f0, a.x), a.y), a.z), a.w);
        }
        acc += (double)((f0 + f1) + (f2 + f3));
    };

    if (blockIdx.x < SCAN_BLOCKS) {
        // ===== one WARP per column; 64-row rounds staged via cp.async, 2-deep =====
        const int k0 = blockIdx.x * 8;
        const int k  = k0 + wrp;

        float carry = 0.0f;
        int   tstop = TM1;
        bool  warp_dead = false;

        auto stage_f = [&](int buf, int rnd) {
            #pragma unroll
            for (int i = 0; i < 2; ++i) {
                const int idx = tid + 256 * i;
                const int row = idx >> 3, col = idx & 7;
                const int tc  = min(rnd * 64 + row, TM1 - 1);
                const unsigned int d = (unsigned int)(col * RPAD + row) * 4u;
                cpa4(smem_u32(&s_liw[buf][0]) + d, tlp + (size_t)(tc + 1) * K_DIM + k0 + col);
                cpa4(smem_u32(&s_r  [buf][0]) + d, r   + (size_t)tc       * K_DIM + k0 + col);
                cpa4(smem_u32(&s_tv [buf][0]) + d, tv  + (size_t)(tc + 1) * K_DIM + k0 + col);
                cpa4(smem_u32(&s_tq [buf][0]) + d, tq  + (size_t)(tc + 1) * K_DIM + k0 + col);
            }
        };
        auto comp_sub = [&](int buf, int rnd, int s) {
            const int  sc = rnd * 2 + s;
            const int  t  = sc * 32 + lane;
            const bool v  = t < TM1;
            const int  ro = s * 32 + lane;
            float liw = s_liw[buf][wrp * RPAD + ro] - (v ? olp[t + 1] : 0.0f);
            float m   = fminf(liw, 0.0f);
            float iw  = expf(m);
            float sv  = v ? (LOGG + m) : 0.0f;
            #pragma unroll
            for (int off = 1; off < 32; off <<= 1) {     // inclusive prefix sum
                float u = __shfl_up_sync(FULLM, sv, off);
                if (lane >= off) sv += u;
            }
            float ls    = carry + sv;
            float decay = expf(ls);                       // underflows to exact 0
            float pdv   = (s_r[buf][wrp * RPAD + ro]
                           + GAMMA * (s_tv[buf][wrp * RPAD + ro]
                                      - iw * s_tq[buf][wrp * RPAD + ro])) * decay;
            if (v) g_dp[(size_t)k * TM1 + t] = make_float2(decay, pdv);
            carry = __shfl_sync(FULLM, ls, 31);
            unsigned bal = __ballot_sync(FULLM, v && decay == 0.0f);
            if (bal && !warp_dead) { tstop = sc * 32 + (__ffs(bal) - 1); warp_dead = true; }
        };

        stage_f(0, 0); CPC();
        stage_f(1, 1); CPC();
        int rnd = 0;
        while (true) {
            CPW(1);                                       // round rnd's tiles landed
            __syncthreads();
            const int buf = rnd & 1;
            if (!warp_dead) comp_sub(buf, rnd, 0);
            if (!warp_dead) comp_sub(buf, rnd, 1);
            const bool allstop = __syncthreads_and(warp_dead) != 0;  // also frees buf
            if (allstop || rnd + 1 >= NRND) break;
            if (rnd + 2 < NRND) stage_f(buf, rnd + 2);
            CPC();
            ++rnd;
        }

        // block-max sub-chunk count for cooperative backward staging
        const int nch = (tstop + 31) >> 5;
        if (lane == 0) s_nch[wrp] = nch;
        __syncthreads();
        int bmax = s_nch[0];
        #pragma unroll
        for (int i = 1; i < 8; ++i) bmax = max(bmax, s_nch[i]);
        const int rmax = (bmax + 1) >> 1;                 // 64-row rounds, >= 1

        // ---- backward: q AND dp tiles via cp.async (fully smem-resident rounds) ----
        // g_dp rows beyond a column's death are exact 0 (written 0 in the death
        // round; never-written rows stay 0 from zero-init and are never made
        // nonzero), so unpredicated suffix sums over staged dp.y are exact.
        auto stage_b = [&](int buf, int rr) {
            #pragma unroll
            for (int i = 0; i < 2; ++i) {
                const int idx = tid + 256 * i;
                const int row = idx >> 3, col = idx & 7;
                const int tc  = min(rr * 64 + row, TM1 - 1);
                const unsigned int d = (unsigned int)(col * RPAD + row) * 4u;
                const float* dpp = (const float*)&g_dp[(size_t)(k0 + col) * TM1 + tc];
                cpa4(smem_u32(&s_liw[buf][0]) + d, q + (size_t)tc * K_DIM + k0 + col);
                cpa4(smem_u32(&s_r  [buf][0]) + d, dpp);       // dp.x plane
                cpa4(smem_u32(&s_tv [buf][0]) + d, dpp + 1);   // dp.y plane
            }
        };

        CPW(0);                                           // drain forward leftovers
        __syncthreads();                                  // buffers free for reuse
        float Rcarry = 0.0f;
        stage_b((rmax - 1) & 1, rmax - 1); CPC();
        for (int rr = rmax - 1; ; --rr) {
            if (rr > 0) { stage_b((rr - 1) & 1, rr - 1); CPC(); CPW(1); }
            else        { CPW(0); }
            __syncthreads();                              // tiles for round rr visible
            const int buf = rr & 1;
            #pragma unroll
            for (int s2 = 1; s2 >= 0; --s2) {             // hi sub-chunk then lo
                const int  sc = 2 * rr + s2;
                const int  t  = sc * 32 + lane;
                const bool v  = (sc < nch) && (t < TM1);
                const int  ro = s2 * 32 + lane;
                float s = s_tv[buf][wrp * RPAD + ro];     // dp.y (0 where invalid)
                #pragma unroll
                for (int off = 1; off < 32; off <<= 1) {  // inclusive suffix sum
                    float u = __shfl_down_sync(FULLM, s, off);
                    if (lane + off < 32) s += u;
                }
                float R    = s + Rcarry;
                float retr = R / fmaxf(s_r[buf][wrp * RPAD + ro], 1e-10f);
                float qv   = s_liw[buf][wrp * RPAD + ro];
                if (v) acc += (double)(sl1(qv, retr) - sl1(qv, 0.0f));
                Rcarry = __shfl_sync(FULLM, R, 0);
            }
            if (rr == 0) break;
            __syncthreads();                              // round rr consumed
        }

        // ---- scan block's half-share of the q sum ----
        qsum_slice(2 * QSUM_BLOCKS + blockIdx.x);
    } else {
        // ---- qsum block: two virtual slices ----
        const int j = blockIdx.x - SCAN_BLOCKS;
        qsum_slice(j);
        qsum_slice(QSUM_BLOCKS + j);
    }

    // ---- deterministic block reduction: warp shuffle tree + fixed-order sum ----
    __shared__ double shw[8];
    #pragma unroll
    for (int off = 16; off > 0; off >>= 1)
        acc += __shfl_xor_sync(FULLM, acc, off);
    __syncthreads();
    if (lane == 0) shw[wrp] = acc;
    __syncthreads();
    double blocksum = 0.0;
    if (tid == 0) {
        #pragma unroll
        for (int i = 0; i < 8; ++i) blocksum += shw[i];
    }

    // ---- fused last-block finalize (deterministic fixed-order final sum) ----
    __shared__ unsigned int sticket;
    if (tid == 0) {
        g_part[blockIdx.x] = blocksum;
        __threadfence();
        sticket = atomicAdd(&g_done, 1u);
    }
    __syncthreads();
    if (sticket == NBLOCKS - 1) {
        __threadfence();
        double a = 0.0;
        for (int i = tid; i < NBLOCKS; i += 256) a += g_part[i];
        __shared__ double sh[256];
        sh[tid] = a;
        __syncthreads();
        #pragma unroll
        for (int s = 128; s > 0; s >>= 1) {
            if (tid < s) sh[tid] += sh[tid + s];
            __syncthreads();
        }
        if (tid == 0) {
            out[0] = (float)(sh[0] / (double)NTOT);
            g_done = 0;                        // reset for next graph replay
        }
    }
}

extern "C" void kernel_launch(void* const* d_in, const int* in_sizes, int n_in,
                              void* d_out, int out_size)
{
    const float* q   = (const float*)d_in[0];  // state_trajectory_action_values (T,K)
    const float* tq  = (const float*)d_in[1];  // target_state_trajectory_action_values (T,K)
    const float* tv  = (const float*)d_in[2];  // target_expected_state_values (T,K)
    const float* r   = (const float*)d_in[3];  // rewards (T,K)
    const float* olp = (const float*)d_in[4];  // original_log_trajectory_action_probs (T,)
    const float* tlp = (const float*)d_in[5];  // target_log_trajectory_task_action_probs (T,K)
    float* out = (float*)d_out;

    retrace_main<<<NBLOCKS, 256>>>(q, tq, tv, r, olp, tlp, out);
}